// round 1
// baseline (speedup 1.0000x reference)
#include <cuda_runtime.h>
#include <cuda_bf16.h>
#include <cstddef>

// CSPN 5x5 guided propagation.
// out[b,y,x] = sum_{dy,dx in [0,5)} w[b, dy*5+dx, y+2, x+2] * src[b, y+2-dy, x+2-dx]
// src = h0 for the center tap (dy=dx=2), hn otherwise; zero padding outside [0,H)x[0,W).

namespace {
constexpr int B  = 4;
constexpr int H  = 352;
constexpr int W  = 1216;
constexpr int K  = 5;
constexpr int KK = K * K;
constexpr int Hp = H + K - 1;   // 356
constexpr int Wp = W + K - 1;   // 1220
constexpr long long CH = (long long)Hp * Wp;  // per-tap channel stride = 434320 (mult of 4)
}

__global__ __launch_bounds__(128)
void cspn_kernel(const float* __restrict__ gw,
                 const float* __restrict__ hn,
                 const float* __restrict__ h0,
                 float* __restrict__ out)
{
    const int gx = blockIdx.x * blockDim.x + threadIdx.x;  // vector-group index
    const int x  = gx * 4;                                 // first of 4 outputs
    if (x >= W) return;
    const int y = blockIdx.y;
    const int b = blockIdx.z;

    // Row-start of guide_weight for tap 0 at output row y, aligned base at column x.
    // We read the two aligned float4 chunks [x..x+3] and [x+4..x+7]; the weights for
    // outputs j=0..3 live at columns x+2..x+5 -> elements {a.z, a.w, c.x, c.y}.
    const float* wbase = gw + (size_t)b * KK * CH + (size_t)(y + 2) * Wp + x;
    const float* hnb   = hn + (size_t)b * H * W;
    const float* h0b   = h0 + (size_t)b * H * W;

    float acc0 = 0.f, acc1 = 0.f, acc2 = 0.f, acc3 = 0.f;

    #pragma unroll
    for (int dy = 0; dy < K; dy++) {
        const int  sy  = y + 2 - dy;
        const bool yok = (sy >= 0) && (sy < H);

        // hn window for this source row: columns x-2 .. x+5 (8 values),
        // covers all 5 dx-shifts for all 4 outputs.
        float hrow[8];
        const float* hnrow = hnb + (size_t)(yok ? sy : 0) * W;
        #pragma unroll
        for (int i = 0; i < 8; i++) {
            const int sx = x - 2 + i;
            hrow[i] = (yok && sx >= 0 && sx < W) ? __ldg(hnrow + sx) : 0.f;
        }

        #pragma unroll
        for (int dx = 0; dx < K; dx++) {
            const int t = dy * K + dx;
            const float4 wa = *reinterpret_cast<const float4*>(wbase + (size_t)t * CH);
            const float4 wc = *reinterpret_cast<const float4*>(wbase + (size_t)t * CH + 4);
            const float w0 = wa.z, w1 = wa.w, w2 = wc.x, w3 = wc.y;

            if (t == (KK - 1) / 2) {
                // Center tap reads h0 at (y, x+j): always in bounds, aligned.
                const float4 hv = *reinterpret_cast<const float4*>(h0b + (size_t)y * W + x);
                acc0 += w0 * hv.x; acc1 += w1 * hv.y;
                acc2 += w2 * hv.z; acc3 += w3 * hv.w;
            } else {
                // src column for output j: x + j + 2 - dx -> hrow[j + 4 - dx]
                const int o = 4 - dx;
                acc0 += w0 * hrow[o + 0];
                acc1 += w1 * hrow[o + 1];
                acc2 += w2 * hrow[o + 2];
                acc3 += w3 * hrow[o + 3];
            }
        }
    }

    *reinterpret_cast<float4*>(out + ((size_t)b * H + y) * W + x) =
        make_float4(acc0, acc1, acc2, acc3);
}

extern "C" void kernel_launch(void* const* d_in, const int* in_sizes, int n_in,
                              void* d_out, int out_size)
{
    const float* gw = (const float*)d_in[0];  // (4, 25, 356, 1220) f32
    const float* hn = (const float*)d_in[1];  // (4, 1, 352, 1216)  f32
    const float* h0 = (const float*)d_in[2];  // (4, 1, 352, 1216)  f32
    float* out = (float*)d_out;               // (4, 1, 352, 1216)  f32

    dim3 block(128, 1, 1);
    dim3 grid((W / 4 + block.x - 1) / block.x, H, B);  // (3, 352, 4)
    cspn_kernel<<<grid, block>>>(gw, hn, h0, out);
}

// round 3
// speedup vs baseline: 1.2755x; 1.2755x over previous
#include <cuda_runtime.h>
#include <cuda_bf16.h>
#include <cstddef>

// CSPN 5x5 guided propagation.
// out[b,y,x] = sum_{dy,dx in [0,5)} w[b, dy*5+dx, y+2, x+2] * src[b, y+2-dy, x+2-dx]
// src = h0 for the center tap (dy=dx=2), hn otherwise; zero padding outside [0,H)x[0,W).
//
// Thread layout: each thread computes 4 outputs at columns x0..x0+3 with
// x0 = 4*g - 2, so the needed weight columns (x0+2 = 4g) are 16B-aligned ->
// exactly one LDG.128 per tap, every byte used. The hn window 4g-4..4g+3 is
// two aligned float4s. Ragged lanes exist only at g=0 and g=NG-1 and are
// exactly the lanes that are never stored.

namespace {
constexpr int B  = 4;
constexpr int H  = 352;
constexpr int W  = 1216;
constexpr int K  = 5;
constexpr int KK = K * K;
constexpr int Hp = H + K - 1;   // 356
constexpr int Wp = W + K - 1;   // 1220
constexpr long long CH = (long long)Hp * Wp;  // per-tap channel stride (mult of 4)
constexpr int NG = W / 4 + 1;   // 305 groups per row (x0 = 4g-2 covers [-2, 1218))
constexpr int TOTAL = NG * H * B;  // 429,440 threads
}

__global__ __launch_bounds__(256)
void cspn_kernel(const float* __restrict__ gw,
                 const float* __restrict__ hn,
                 const float* __restrict__ h0,
                 float* __restrict__ out)
{
    const int idx = blockIdx.x * blockDim.x + threadIdx.x;
    if (idx >= TOTAL) return;

    const int g   = idx % NG;
    const int rem = idx / NG;
    const int y   = rem % H;
    const int b   = rem / H;

    const int xw = 4 * g;      // aligned weight column (= x0 + 2)
    const int x0 = xw - 2;     // first output column (may be -2 at g=0)

    const float* wp  = gw + (size_t)b * KK * CH + (size_t)(y + 2) * Wp + xw;
    const float* hnb = hn + (size_t)b * H * W;
    const float* h0r = h0 + ((size_t)b * H + y) * W;

    const bool lo_ok = (g > 0);        // columns x0, x0+1 in-bounds
    const bool hi_ok = (g < NG - 1);   // columns x0+2, x0+3 in-bounds

    float acc0 = 0.f, acc1 = 0.f, acc2 = 0.f, acc3 = 0.f;

    #pragma unroll
    for (int dy = 0; dy < K; dy++) {
        const int  sy  = y + 2 - dy;
        const bool yok = ((unsigned)sy < (unsigned)H);
        const float* hr = hnb + (size_t)(yok ? sy : 0) * W;

        // hn window columns 4g-4 .. 4g+3: two aligned float4s, each either
        // fully in-bounds or fully outside [0, W).
        float4 v0 = (yok && lo_ok) ? *reinterpret_cast<const float4*>(hr + xw - 4)
                                   : make_float4(0.f, 0.f, 0.f, 0.f);
        float4 v1 = (yok && hi_ok) ? *reinterpret_cast<const float4*>(hr + xw)
                                   : make_float4(0.f, 0.f, 0.f, 0.f);
        const float hrow[8] = {v0.x, v0.y, v0.z, v0.w, v1.x, v1.y, v1.z, v1.w};

        #pragma unroll
        for (int dx = 0; dx < K; dx++) {
            const int t = dy * K + dx;
            const float4 w = *reinterpret_cast<const float4*>(wp + (size_t)t * CH);

            if (t == (KK - 1) / 2) {
                // Center tap reads h0 at columns x0..x0+3 (8B-aligned pairs).
                float2 hlo = lo_ok ? *reinterpret_cast<const float2*>(h0r + x0)
                                   : make_float2(0.f, 0.f);
                float2 hhi = hi_ok ? *reinterpret_cast<const float2*>(h0r + x0 + 2)
                                   : make_float2(0.f, 0.f);
                acc0 += w.x * hlo.x; acc1 += w.y * hlo.y;
                acc2 += w.z * hhi.x; acc3 += w.w * hhi.y;
            } else {
                // src column for output j is x0 + j + 2 - dx -> hrow[j + 4 - dx]
                const int o = 4 - dx;
                acc0 += w.x * hrow[o + 0];
                acc1 += w.y * hrow[o + 1];
                acc2 += w.z * hrow[o + 2];
                acc3 += w.w * hrow[o + 3];
            }
        }
    }

    float* orow = out + ((size_t)b * H + y) * W;
    if (lo_ok) *reinterpret_cast<float2*>(orow + x0)     = make_float2(acc0, acc1);
    if (hi_ok) *reinterpret_cast<float2*>(orow + x0 + 2) = make_float2(acc2, acc3);
}

extern "C" void kernel_launch(void* const* d_in, const int* in_sizes, int n_in,
                              void* d_out, int out_size)
{
    const float* gw = (const float*)d_in[0];  // (4, 25, 356, 1220) f32
    const float* hn = (const float*)d_in[1];  // (4, 1, 352, 1216)  f32
    const float* h0 = (const float*)d_in[2];  // (4, 1, 352, 1216)  f32
    float* out = (float*)d_out;               // (4, 1, 352, 1216)  f32

    const int threads = 256;
    const int blocks  = (TOTAL + threads - 1) / threads;  // 1678
    cspn_kernel<<<blocks, threads>>>(gw, hn, h0, out);
}

// round 5
// speedup vs baseline: 1.3420x; 1.0522x over previous
#include <cuda_runtime.h>
#include <cuda_bf16.h>
#include <cstddef>

// CSPN 5x5 guided propagation, 8 outputs per thread.
// out[b,y,x] = sum_{dy,dx} w[b, dy*5+dx, y+2, x+2] * src[b, y+2-dy, x+2-dx]
// src = h0 at center tap, hn otherwise; zero padding outside [0,H)x[0,W).
//
// x0 = 8g - 2 so weight columns x0+2..x0+9 = 8g..8g+7 are two aligned
// float4s per tap (no duplicated bytes). hn window 8g-4..8g+7 is three
// aligned float4s; every edge vector is fully in-bounds or fully out.
// Weights stream with __ldcs (L2 evict-first); hn/h0 use __ldg (reused,
// L2-resident).

namespace {
constexpr int B  = 4;
constexpr int H  = 352;
constexpr int W  = 1216;
constexpr int K  = 5;
constexpr int KK = K * K;
constexpr int Hp = H + K - 1;   // 356
constexpr int Wp = W + K - 1;   // 1220
constexpr long long CH = (long long)Hp * Wp;  // per-tap channel stride
constexpr int NG = W / 8 + 1;      // 153 groups per row
constexpr int TOTAL = NG * H * B;  // 215,424 threads
}

__global__ __launch_bounds__(256)
void cspn_kernel8(const float* __restrict__ gw,
                  const float* __restrict__ hn,
                  const float* __restrict__ h0,
                  float* __restrict__ out)
{
    const int idx = blockIdx.x * blockDim.x + threadIdx.x;
    if (idx >= TOTAL) return;

    const int g   = idx % NG;
    const int rem = idx / NG;
    const int y   = rem % H;
    const int b   = rem / H;

    const int xw = 8 * g;      // aligned weight/window base column
    const int x0 = xw - 2;     // first output column

    const float* wp  = gw + (size_t)b * KK * CH + (size_t)(y + 2) * Wp + xw;
    const float* hnb = hn + (size_t)b * H * W;
    const float* h0r = h0 + ((size_t)b * H + y) * W;

    const bool lo_ok = (g > 0);        // outputs j=0,1 (cols x0,x0+1)
    const bool hi_ok = (g < NG - 1);   // outputs j=2..7 (cols 8g..8g+5)

    float acc[8] = {0.f, 0.f, 0.f, 0.f, 0.f, 0.f, 0.f, 0.f};

    #pragma unroll
    for (int dy = 0; dy < K; dy++) {
        const int  sy  = y + 2 - dy;
        const bool yok = ((unsigned)sy < (unsigned)H);
        const float* hr = hnb + (size_t)(yok ? sy : 0) * W;

        // hn window: cols 8g-4 .. 8g+7, three aligned float4s, all-or-nothing.
        const float4 z4 = make_float4(0.f, 0.f, 0.f, 0.f);
        float4 v0 = (yok && lo_ok) ? __ldg(reinterpret_cast<const float4*>(hr + xw - 4)) : z4;
        float4 v1 = (yok && hi_ok) ? __ldg(reinterpret_cast<const float4*>(hr + xw))     : z4;
        float4 v2 = (yok && hi_ok) ? __ldg(reinterpret_cast<const float4*>(hr + xw + 4)) : z4;
        const float hrow[12] = {v0.x, v0.y, v0.z, v0.w,
                                v1.x, v1.y, v1.z, v1.w,
                                v2.x, v2.y, v2.z, v2.w};

        #pragma unroll
        for (int dx = 0; dx < K; dx++) {
            const int t = dy * K + dx;
            const float4 wa = __ldcs(reinterpret_cast<const float4*>(wp + (size_t)t * CH));
            const float4 wb = __ldcs(reinterpret_cast<const float4*>(wp + (size_t)t * CH + 4));
            const float wv[8] = {wa.x, wa.y, wa.z, wa.w, wb.x, wb.y, wb.z, wb.w};

            if (t == (KK - 1) / 2) {
                // Center tap: h0 at cols x0..x0+7, four 8B-aligned pairs.
                const float2 z2 = make_float2(0.f, 0.f);
                float2 p0 = lo_ok ? __ldg(reinterpret_cast<const float2*>(h0r + x0))     : z2;
                float2 p1 = hi_ok ? __ldg(reinterpret_cast<const float2*>(h0r + x0 + 2)) : z2;
                float2 p2 = hi_ok ? __ldg(reinterpret_cast<const float2*>(h0r + x0 + 4)) : z2;
                float2 p3 = hi_ok ? __ldg(reinterpret_cast<const float2*>(h0r + x0 + 6)) : z2;
                const float hc[8] = {p0.x, p0.y, p1.x, p1.y, p2.x, p2.y, p3.x, p3.y};
                #pragma unroll
                for (int j = 0; j < 8; j++) acc[j] += wv[j] * hc[j];
            } else {
                // src col for output j: x0 + j + 2 - dx = xw + j - dx
                // window index: (xw + j - dx) - (xw - 4) = j + 4 - dx
                const int o = 4 - dx;
                #pragma unroll
                for (int j = 0; j < 8; j++) acc[j] += wv[j] * hrow[o + j];
            }
        }
    }

    float* orow = out + ((size_t)b * H + y) * W;
    if (lo_ok) *reinterpret_cast<float2*>(orow + x0)     = make_float2(acc[0], acc[1]);
    if (hi_ok) {
        *reinterpret_cast<float2*>(orow + x0 + 2) = make_float2(acc[2], acc[3]);
        *reinterpret_cast<float2*>(orow + x0 + 4) = make_float2(acc[4], acc[5]);
        *reinterpret_cast<float2*>(orow + x0 + 6) = make_float2(acc[6], acc[7]);
    }
}

extern "C" void kernel_launch(void* const* d_in, const int* in_sizes, int n_in,
                              void* d_out, int out_size)
{
    const float* gw = (const float*)d_in[0];  // (4, 25, 356, 1220) f32
    const float* hn = (const float*)d_in[1];  // (4, 1, 352, 1216)  f32
    const float* h0 = (const float*)d_in[2];  // (4, 1, 352, 1216)  f32
    float* out = (float*)d_out;               // (4, 1, 352, 1216)  f32

    const int threads = 256;
    const int blocks  = (TOTAL + threads - 1) / threads;  // 842
    cspn_kernel8<<<blocks, threads>>>(gw, hn, h0, out);
}